// round 8
// baseline (speedup 1.0000x reference)
#include <cuda_runtime.h>
#include <cuda_bf16.h>
#include <cuda_fp16.h>
#include <math.h>

#define NN 10000
#define NE 256000
#define HH 128
#define H2 256
#define H3 384
#define NR 20

typedef unsigned int u32;

// ---------------- scratch (static device globals; no allocation) ----------------
__device__ __half g_x16[NN * H3];                  // node MLP out, fp16
__device__ __half g_mu16[NN * 3 * HH];             // mu converted to fp16 (for gathers)
__device__ __half g_filters[(size_t)NE * H3];      // fp16 filters (196 MB)
__device__ u32   g_bhp[(HH / 2) * H3];             // Wf2 hi (k-pair packed bf16x2)
__device__ u32   g_blp[(HH / 2) * H3];             // Wf2 lo
__device__ u32   g_i1h[(HH / 2) * H3];
__device__ u32   g_i1l[(HH / 2) * H3];
__device__ u32   g_i2h[(H3 / 2) * H3];
__device__ u32   g_i2l[(H3 / 2) * H3];
__device__ u32   g_vch[(HH / 2) * H2];
__device__ u32   g_vcl[(HH / 2) * H2];
__device__ u32   g_m1h[(H2 / 2) * H3];
__device__ u32   g_m1l[(H2 / 2) * H3];
__device__ u32   g_m2h[(H3 / 2) * H3];
__device__ u32   g_m2l[(H3 / 2) * H3];
__device__ float g_qmid[NN * HH];
__device__ float g_mumid[NN * 3 * HH];
__device__ float g_vnorm[NN * HH];
__device__ float g_inner[NN * HH];
__device__ float g_muw[NN * 3 * HH];
__device__ int   g_count[NN];
__device__ int   g_off[NN + 1];
__device__ int   g_cursor[NN];
__device__ int   g_elist[NE];

__device__ __forceinline__ float silu_f(float x) {
    return x / (1.0f + __expf(-x));
}

__device__ __forceinline__ u32 pack_bf16x2(float lo, float hi) {
    u32 r;
    asm("cvt.rn.bf16x2.f32 %0, %1, %2;" : "=r"(r) : "f"(hi), "f"(lo));
    return r;
}

__device__ __forceinline__ void mma_bf16(float& c0, float& c1, float& c2, float& c3,
                                         u32 a0, u32 a1, u32 a2, u32 a3,
                                         u32 b0, u32 b1) {
    asm("mma.sync.aligned.m16n8k16.row.col.f32.bf16.bf16.f32 "
        "{%0,%1,%2,%3}, {%4,%5,%6,%7}, {%8,%9}, {%0,%1,%2,%3};"
        : "+f"(c0), "+f"(c1), "+f"(c2), "+f"(c3)
        : "r"(a0), "r"(a1), "r"(a2), "r"(a3), "r"(b0), "r"(b1));
}

__device__ __forceinline__ void split_a(float2 f, u32& hi, u32& lo) {
    hi = pack_bf16x2(f.x, f.y);
    lo = pack_bf16x2(f.x - __uint_as_float(hi << 16),
                     f.y - __uint_as_float(hi & 0xFFFF0000u));
}

// split two f32 values into packed hi/lo bf16x2
__device__ __forceinline__ void split_pair(float v0, float v1, u32& hi, u32& lo) {
    hi = pack_bf16x2(v0, v1);
    lo = pack_bf16x2(v0 - __uint_as_float(hi << 16),
                     v1 - __uint_as_float(hi & 0xFFFF0000u));
}

// ---------------- weight split (one-shot, tiny). W is [2*kpairs, width] ----------------
__global__ void k_splitw(const float* __restrict__ W, u32* __restrict__ hi,
                         u32* __restrict__ lo, int kpairs, int width) {
    int i = blockIdx.x * blockDim.x + threadIdx.x;
    if (i < kpairs * width) {
        int p = i / width, col = i % width;
        float w0 = W[(2 * p) * width + col];
        float w1 = W[(2 * p + 1) * width + col];
        u32 h01 = pack_bf16x2(w0, w1);
        float h0 = __uint_as_float(h01 << 16);
        float h1 = __uint_as_float(h01 & 0xFFFF0000u);
        hi[i] = h01;
        lo[i] = pack_bf16x2(w0 - h0, w1 - h1);
    }
}

// ---------------- mu -> fp16 (one-shot) ----------------
__global__ void k_mu2h(const float* __restrict__ mu) {
    int i = blockIdx.x * blockDim.x + threadIdx.x;
    if (i < NN * 3 * HH) g_mu16[i] = __float2half(mu[i]);
}

// ---------------- CSR build ----------------
__global__ void k_zero() {
    int i = blockIdx.x * blockDim.x + threadIdx.x;
    if (i < NN) g_count[i] = 0;
}

__global__ void k_count(const int* __restrict__ ei) {
    for (int e = blockIdx.x * blockDim.x + threadIdx.x; e < NE;
         e += gridDim.x * blockDim.x)
        atomicAdd(&g_count[ei[e]], 1);
}

__global__ __launch_bounds__(1024) void k_scan() {
    __shared__ int ps[1024];
    int tid = threadIdx.x;
    const int CH = (NN + 1023) / 1024;
    int base = tid * CH;
    int s = 0;
    for (int j = 0; j < CH; ++j) {
        int idx = base + j;
        if (idx < NN) s += g_count[idx];
    }
    ps[tid] = s;
    __syncthreads();
    for (int off = 1; off < 1024; off <<= 1) {
        int v = 0;
        if (tid >= off) v = ps[tid - off];
        __syncthreads();
        ps[tid] += v;
        __syncthreads();
    }
    int run = ps[tid] - s;
    for (int j = 0; j < CH; ++j) {
        int idx = base + j;
        if (idx < NN) {
            g_off[idx] = run;
            g_cursor[idx] = run;
            run += g_count[idx];
        }
    }
    if (tid == 1023) g_off[NN] = ps[1023];
}

__global__ void k_fill(const int* __restrict__ ei) {
    for (int e = blockIdx.x * blockDim.x + threadIdx.x; e < NE;
         e += gridDim.x * blockDim.x) {
        int t = ei[e];
        int pos = atomicAdd(&g_cursor[t], 1);
        g_elist[pos] = e;
    }
}

// ---------------- node inter MLP via bf16 split mma ----------------
#define SQP 132
#define SH2P 388
#define NODE_SMEM ((32 * SQP + 32 * SH2P) * 4)
__global__ __launch_bounds__(256) void k_node_mlp(
    const float* __restrict__ q,
    const float* __restrict__ b1, const float* __restrict__ b2)
{
    extern __shared__ float smn[];
    float* sq = smn;
    float* sh = smn + 32 * SQP;
    int tid = threadIdx.x;
    int n0 = blockIdx.x * 32;

    for (int i = tid; i < 32 * HH; i += 256) {
        int r = i >> 7, c = i & 127;
        int n = n0 + r;
        sq[r * SQP + c] = (n < NN) ? q[n * HH + c] : 0.f;
    }
    __syncthreads();

    int wid  = tid >> 5;
    int lane = tid & 31;
    int gid  = lane >> 2;
    int tig  = lane & 3;
    int nbase = wid * 48;

    {
        float acc[2][6][4];
        #pragma unroll
        for (int r = 0; r < 2; ++r)
            #pragma unroll
            for (int t = 0; t < 6; ++t)
                #pragma unroll
                for (int c = 0; c < 4; ++c) acc[r][t][c] = 0.f;

        #pragma unroll 1
        for (int k0 = 0; k0 < HH; k0 += 16) {
            int kp = k0 >> 1;
            u32 bh[6][2], bl[6][2];
            #pragma unroll
            for (int t = 0; t < 6; ++t) {
                int col = nbase + t * 8 + gid;
                int i0 = (kp + tig) * H3 + col;
                int i1 = (kp + 4 + tig) * H3 + col;
                bh[t][0] = __ldg(&g_i1h[i0]);
                bh[t][1] = __ldg(&g_i1h[i1]);
                bl[t][0] = __ldg(&g_i1l[i0]);
                bl[t][1] = __ldg(&g_i1l[i1]);
            }
            #pragma unroll
            for (int r = 0; r < 2; ++r) {
                int rb = r * 16;
                float2 f0 = *(const float2*)&sq[(rb + gid)     * SQP + k0 + 2 * tig];
                float2 f1 = *(const float2*)&sq[(rb + gid + 8) * SQP + k0 + 2 * tig];
                float2 f2 = *(const float2*)&sq[(rb + gid)     * SQP + k0 + 8 + 2 * tig];
                float2 f3 = *(const float2*)&sq[(rb + gid + 8) * SQP + k0 + 8 + 2 * tig];
                u32 ah0, al0, ah1, al1, ah2, al2, ah3, al3;
                split_a(f0, ah0, al0); split_a(f1, ah1, al1);
                split_a(f2, ah2, al2); split_a(f3, ah3, al3);
                #pragma unroll
                for (int t = 0; t < 6; ++t) {
                    mma_bf16(acc[r][t][0], acc[r][t][1], acc[r][t][2], acc[r][t][3],
                             ah0, ah1, ah2, ah3, bh[t][0], bh[t][1]);
                    mma_bf16(acc[r][t][0], acc[r][t][1], acc[r][t][2], acc[r][t][3],
                             al0, al1, al2, al3, bh[t][0], bh[t][1]);
                    mma_bf16(acc[r][t][0], acc[r][t][1], acc[r][t][2], acc[r][t][3],
                             ah0, ah1, ah2, ah3, bl[t][0], bl[t][1]);
                }
            }
        }
        #pragma unroll
        for (int r = 0; r < 2; ++r) {
            int row0 = r * 16 + gid;
            int row1 = row0 + 8;
            #pragma unroll
            for (int t = 0; t < 6; ++t) {
                int col = nbase + t * 8 + 2 * tig;
                float b0v = __ldg(&b1[col]);
                float b1v = __ldg(&b1[col + 1]);
                sh[row0 * SH2P + col]     = silu_f(acc[r][t][0] + b0v);
                sh[row0 * SH2P + col + 1] = silu_f(acc[r][t][1] + b1v);
                sh[row1 * SH2P + col]     = silu_f(acc[r][t][2] + b0v);
                sh[row1 * SH2P + col + 1] = silu_f(acc[r][t][3] + b1v);
            }
        }
    }
    __syncthreads();

    {
        float acc[2][6][4];
        #pragma unroll
        for (int r = 0; r < 2; ++r)
            #pragma unroll
            for (int t = 0; t < 6; ++t)
                #pragma unroll
                for (int c = 0; c < 4; ++c) acc[r][t][c] = 0.f;

        #pragma unroll 1
        for (int k0 = 0; k0 < H3; k0 += 16) {
            int kp = k0 >> 1;
            u32 bh[6][2], bl[6][2];
            #pragma unroll
            for (int t = 0; t < 6; ++t) {
                int col = nbase + t * 8 + gid;
                int i0 = (kp + tig) * H3 + col;
                int i1 = (kp + 4 + tig) * H3 + col;
                bh[t][0] = __ldg(&g_i2h[i0]);
                bh[t][1] = __ldg(&g_i2h[i1]);
                bl[t][0] = __ldg(&g_i2l[i0]);
                bl[t][1] = __ldg(&g_i2l[i1]);
            }
            #pragma unroll
            for (int r = 0; r < 2; ++r) {
                int rb = r * 16;
                float2 f0 = *(const float2*)&sh[(rb + gid)     * SH2P + k0 + 2 * tig];
                float2 f1 = *(const float2*)&sh[(rb + gid + 8) * SH2P + k0 + 2 * tig];
                float2 f2 = *(const float2*)&sh[(rb + gid)     * SH2P + k0 + 8 + 2 * tig];
                float2 f3 = *(const float2*)&sh[(rb + gid + 8) * SH2P + k0 + 8 + 2 * tig];
                u32 ah0, al0, ah1, al1, ah2, al2, ah3, al3;
                split_a(f0, ah0, al0); split_a(f1, ah1, al1);
                split_a(f2, ah2, al2); split_a(f3, ah3, al3);
                #pragma unroll
                for (int t = 0; t < 6; ++t) {
                    mma_bf16(acc[r][t][0], acc[r][t][1], acc[r][t][2], acc[r][t][3],
                             ah0, ah1, ah2, ah3, bh[t][0], bh[t][1]);
                    mma_bf16(acc[r][t][0], acc[r][t][1], acc[r][t][2], acc[r][t][3],
                             al0, al1, al2, al3, bh[t][0], bh[t][1]);
                    mma_bf16(acc[r][t][0], acc[r][t][1], acc[r][t][2], acc[r][t][3],
                             ah0, ah1, ah2, ah3, bl[t][0], bl[t][1]);
                }
            }
        }
        #pragma unroll
        for (int r = 0; r < 2; ++r) {
            int row0 = r * 16 + gid;
            int row1 = row0 + 8;
            #pragma unroll
            for (int t = 0; t < 6; ++t) {
                int col = nbase + t * 8 + 2 * tig;
                float b0v = __ldg(&b2[col]);
                float b1v = __ldg(&b2[col + 1]);
                if (n0 + row0 < NN)
                    *(__half2*)&g_x16[(size_t)(n0 + row0) * H3 + col] =
                        __floats2half2_rn(acc[r][t][0] + b0v, acc[r][t][1] + b1v);
                if (n0 + row1 < NN)
                    *(__half2*)&g_x16[(size_t)(n0 + row1) * H3 + col] =
                        __floats2half2_rn(acc[r][t][2] + b0v, acc[r][t][3] + b1v);
            }
        }
    }
}

// ---------------- edge filter MLP: phase1 scalar + pre-split, phase2 bf16 mma ----------------
// hidden stored PRE-SPLIT as packed bf16x2 k-pairs, layout [row][kp], stride 68.
#define KPS 68
__global__ __launch_bounds__(256) void k_edge_filter(
    const float* __restrict__ rbf, const float* __restrict__ cut,
    const float* __restrict__ Wf1, const float* __restrict__ bf1,
    const float* __restrict__ bf2)
{
    __shared__ float srb[64][NR];
    __shared__ float scut[64];
    __shared__ u32 shiT[64 * KPS];   // hidden hi, [row][kp]
    __shared__ u32 sloT[64 * KPS];   // hidden lo
    int tid = threadIdx.x;
    int e0 = blockIdx.x * 64;

    for (int i = tid; i < 64 * NR; i += 256)
        srb[i / NR][i % NR] = rbf[(e0 + i / NR) * NR + (i % NR)];
    if (tid < 64) scut[tid] = cut[e0 + tid];
    __syncthreads();

    // phase 1 (scalar, K=20) + split epilogue
    {
        int rg = tid >> 4;
        int cg = tid & 15;
        int r0 = rg * 4;
        for (int pass = 0; pass < 2; ++pass) {
            int c0 = cg * 4 + pass * 64;
            float acc[4][4] = {};
            for (int k = 0; k < NR; ++k) {
                float4 w = *reinterpret_cast<const float4*>(&Wf1[k * HH + c0]);
                #pragma unroll
                for (int i = 0; i < 4; ++i) {
                    float s = srb[r0 + i][k];
                    acc[i][0] = fmaf(s, w.x, acc[i][0]);
                    acc[i][1] = fmaf(s, w.y, acc[i][1]);
                    acc[i][2] = fmaf(s, w.z, acc[i][2]);
                    acc[i][3] = fmaf(s, w.w, acc[i][3]);
                }
            }
            int kp0 = c0 >> 1;
            #pragma unroll
            for (int i = 0; i < 4; ++i) {
                float v0 = silu_f(acc[i][0] + bf1[c0]);
                float v1 = silu_f(acc[i][1] + bf1[c0 + 1]);
                float v2 = silu_f(acc[i][2] + bf1[c0 + 2]);
                float v3 = silu_f(acc[i][3] + bf1[c0 + 3]);
                u32 h0, l0, h1, l1;
                split_pair(v0, v1, h0, l0);
                split_pair(v2, v3, h1, l1);
                shiT[(r0 + i) * KPS + kp0]     = h0;
                sloT[(r0 + i) * KPS + kp0]     = l0;
                shiT[(r0 + i) * KPS + kp0 + 1] = h1;
                sloT[(r0 + i) * KPS + kp0 + 1] = l1;
            }
        }
    }
    __syncthreads();

    // phase 2: A fragments are direct LDS.32 (conflict-free: bank = 4*gid + tig)
    int wid  = tid >> 5;
    int lane = tid & 31;
    int gid  = lane >> 2;
    int tig  = lane & 3;
    int nbase = wid * 48;

    float acc[4][6][4];
    #pragma unroll
    for (int r = 0; r < 4; ++r)
        #pragma unroll
        for (int t = 0; t < 6; ++t)
            #pragma unroll
            for (int c = 0; c < 4; ++c) acc[r][t][c] = 0.f;

    #pragma unroll 1
    for (int k0 = 0; k0 < HH; k0 += 16) {
        int kp = k0 >> 1;
        u32 bh[6][2], bl[6][2];
        #pragma unroll
        for (int t = 0; t < 6; ++t) {
            int col = nbase + t * 8 + gid;
            int i0 = (kp + tig) * H3 + col;
            int i1 = (kp + 4 + tig) * H3 + col;
            bh[t][0] = __ldg(&g_bhp[i0]);
            bh[t][1] = __ldg(&g_bhp[i1]);
            bl[t][0] = __ldg(&g_blp[i0]);
            bl[t][1] = __ldg(&g_blp[i1]);
        }
        #pragma unroll
        for (int r = 0; r < 4; ++r) {
            int rb = r * 16;
            int ra = (rb + gid) * KPS;
            int rc = (rb + gid + 8) * KPS;
            u32 ah0 = shiT[ra + kp + tig];
            u32 ah1 = shiT[rc + kp + tig];
            u32 ah2 = shiT[ra + kp + 4 + tig];
            u32 ah3 = shiT[rc + kp + 4 + tig];
            u32 al0 = sloT[ra + kp + tig];
            u32 al1 = sloT[rc + kp + tig];
            u32 al2 = sloT[ra + kp + 4 + tig];
            u32 al3 = sloT[rc + kp + 4 + tig];
            #pragma unroll
            for (int t = 0; t < 6; ++t) {
                mma_bf16(acc[r][t][0], acc[r][t][1], acc[r][t][2], acc[r][t][3],
                         ah0, ah1, ah2, ah3, bh[t][0], bh[t][1]);
                mma_bf16(acc[r][t][0], acc[r][t][1], acc[r][t][2], acc[r][t][3],
                         al0, al1, al2, al3, bh[t][0], bh[t][1]);
                mma_bf16(acc[r][t][0], acc[r][t][1], acc[r][t][2], acc[r][t][3],
                         ah0, ah1, ah2, ah3, bl[t][0], bl[t][1]);
            }
        }
    }

    #pragma unroll
    for (int r = 0; r < 4; ++r) {
        int row0 = r * 16 + gid;
        int row1 = row0 + 8;
        float c0v = scut[row0];
        float c1v = scut[row1];
        #pragma unroll
        for (int t = 0; t < 6; ++t) {
            int col = nbase + t * 8 + 2 * tig;
            float b0v = bf2[col];
            float b1v = bf2[col + 1];
            __half2 v0 = __floats2half2_rn((acc[r][t][0] + b0v) * c0v,
                                           (acc[r][t][1] + b1v) * c0v);
            __half2 v1 = __floats2half2_rn((acc[r][t][2] + b0v) * c1v,
                                           (acc[r][t][3] + b1v) * c1v);
            *(__half2*)&g_filters[(size_t)(e0 + row0) * H3 + col] = v0;
            *(__half2*)&g_filters[(size_t)(e0 + row1) * H3 + col] = v1;
        }
    }
}

// ---------------- pull aggregation (CSR) -> qmid, mumid ----------------
__global__ __launch_bounds__(128) void k_aggregate(
    const float* __restrict__ q, const float* __restrict__ mu,
    const int* __restrict__ ei, const float* __restrict__ uv)
{
    int n = blockIdx.x;
    int h = threadIdx.x;
    int beg = g_off[n], end = g_off[n + 1];
    float qa = 0.f, m0 = 0.f, m1 = 0.f, m2 = 0.f;
    for (int i = beg; i < end; ++i) {
        int e = g_elist[i];
        int s = ei[NE + e];
        const __half* f = &g_filters[(size_t)e * H3];
        float fq = __half2float(f[h]);
        float fr = __half2float(f[HH + h]);
        float fm = __half2float(f[2 * HH + h]);
        const __half* xs = &g_x16[s * H3];
        float xq = __half2float(xs[h]) * fq;
        float xr = __half2float(xs[HH + h]) * fr;
        float xm = __half2float(xs[2 * HH + h]) * fm;
        float u0 = uv[e * 3 + 0], u1 = uv[e * 3 + 1], u2 = uv[e * 3 + 2];
        const __half* ms = &g_mu16[s * 3 * HH];
        qa += xq;
        m0 = fmaf(u0, xr, fmaf(__half2float(ms[h]),          xm, m0));
        m1 = fmaf(u1, xr, fmaf(__half2float(ms[HH + h]),     xm, m1));
        m2 = fmaf(u2, xr, fmaf(__half2float(ms[2 * HH + h]), xm, m2));
    }
    g_qmid[n * HH + h] = q[n * HH + h] + qa;
    g_mumid[n * 3 * HH + h]          = mu[n * 3 * HH + h] + m0;
    g_mumid[n * 3 * HH + HH + h]     = mu[n * 3 * HH + HH + h] + m1;
    g_mumid[n * 3 * HH + 2 * HH + h] = mu[n * 3 * HH + 2 * HH + h] + m2;
}

// ---------------- equivariant linear via bf16 split mma ----------------
#define EMP 132
#define EOP 260
#define EQ_SMEM ((48 * EMP + 48 * EOP) * 4)
__global__ __launch_bounds__(256) void k_equiv()
{
    extern __shared__ float sme[];
    float* smu  = sme;
    float* sout = sme + 48 * EMP;
    int tid = threadIdx.x;
    int n0 = blockIdx.x * 16;
    int row_base = n0 * 3;

    for (int i = tid; i < 48 * HH; i += 256) {
        int r = i >> 7, c = i & 127;
        int grow = row_base + r;
        smu[r * EMP + c] = (grow < NN * 3) ? g_mumid[grow * HH + c] : 0.f;
    }
    __syncthreads();

    int wid  = tid >> 5;
    int lane = tid & 31;
    int gid  = lane >> 2;
    int tig  = lane & 3;
    int nbase = wid * 32;

    float acc[3][4][4];
    #pragma unroll
    for (int r = 0; r < 3; ++r)
        #pragma unroll
        for (int t = 0; t < 4; ++t)
            #pragma unroll
            for (int c = 0; c < 4; ++c) acc[r][t][c] = 0.f;

    #pragma unroll 1
    for (int k0 = 0; k0 < HH; k0 += 16) {
        int kp = k0 >> 1;
        u32 bh[4][2], bl[4][2];
        #pragma unroll
        for (int t = 0; t < 4; ++t) {
            int col = nbase + t * 8 + gid;
            int i0 = (kp + tig) * H2 + col;
            int i1 = (kp + 4 + tig) * H2 + col;
            bh[t][0] = __ldg(&g_vch[i0]);
            bh[t][1] = __ldg(&g_vch[i1]);
            bl[t][0] = __ldg(&g_vcl[i0]);
            bl[t][1] = __ldg(&g_vcl[i1]);
        }
        #pragma unroll
        for (int r = 0; r < 3; ++r) {
            int rb = r * 16;
            float2 f0 = *(const float2*)&smu[(rb + gid)     * EMP + k0 + 2 * tig];
            float2 f1 = *(const float2*)&smu[(rb + gid + 8) * EMP + k0 + 2 * tig];
            float2 f2 = *(const float2*)&smu[(rb + gid)     * EMP + k0 + 8 + 2 * tig];
            float2 f3 = *(const float2*)&smu[(rb + gid + 8) * EMP + k0 + 8 + 2 * tig];
            u32 ah0, al0, ah1, al1, ah2, al2, ah3, al3;
            split_a(f0, ah0, al0); split_a(f1, ah1, al1);
            split_a(f2, ah2, al2); split_a(f3, ah3, al3);
            #pragma unroll
            for (int t = 0; t < 4; ++t) {
                mma_bf16(acc[r][t][0], acc[r][t][1], acc[r][t][2], acc[r][t][3],
                         ah0, ah1, ah2, ah3, bh[t][0], bh[t][1]);
                mma_bf16(acc[r][t][0], acc[r][t][1], acc[r][t][2], acc[r][t][3],
                         al0, al1, al2, al3, bh[t][0], bh[t][1]);
                mma_bf16(acc[r][t][0], acc[r][t][1], acc[r][t][2], acc[r][t][3],
                         ah0, ah1, ah2, ah3, bl[t][0], bl[t][1]);
            }
        }
    }

    #pragma unroll
    for (int r = 0; r < 3; ++r) {
        int row0 = r * 16 + gid;
        int row1 = row0 + 8;
        #pragma unroll
        for (int t = 0; t < 4; ++t) {
            int col = nbase + t * 8 + 2 * tig;
            sout[row0 * EOP + col]     = acc[r][t][0];
            sout[row0 * EOP + col + 1] = acc[r][t][1];
            sout[row1 * EOP + col]     = acc[r][t][2];
            sout[row1 * EOP + col + 1] = acc[r][t][3];
        }
    }
    __syncthreads();

    for (int slot = tid; slot < 16 * HH; slot += 256) {
        int r = slot >> 7;
        int o = slot & 127;
        int n = n0 + r;
        if (n >= NN) break;
        float v0 = sout[(r * 3 + 0) * EOP + o];
        float v1 = sout[(r * 3 + 1) * EOP + o];
        float v2 = sout[(r * 3 + 2) * EOP + o];
        float w0 = sout[(r * 3 + 0) * EOP + HH + o];
        float w1 = sout[(r * 3 + 1) * EOP + HH + o];
        float w2 = sout[(r * 3 + 2) * EOP + HH + o];
        g_vnorm[n * HH + o] = sqrtf(v0 * v0 + v1 * v1 + v2 * v2 + 1e-8f);
        g_inner[n * HH + o] = v0 * w0 + v1 * w1 + v2 * w2;
        g_muw[n * 3 * HH + o]          = w0;
        g_muw[n * 3 * HH + HH + o]     = w1;
        g_muw[n * 3 * HH + 2 * HH + o] = w2;
    }
}

// ---------------- scalar mix MLP via bf16 split mma + final update ----------------
#define MXP 388
#define MIX_SMEM ((32 * MXP * 2) * 4)
__global__ __launch_bounds__(256) void k_mix(
    const float* __restrict__ bm1, const float* __restrict__ bm2,
    float* __restrict__ qout, float* __restrict__ muout)
{
    extern __shared__ float smx[];
    float* sA = smx;
    float* sB = smx + 32 * MXP;
    int tid = threadIdx.x;
    int n0 = blockIdx.x * 32;

    for (int i = tid; i < 32 * H2; i += 256) {
        int r = i >> 8, c = i & 255;
        int n = n0 + r;
        float v = 0.f;
        if (n < NN) v = (c < HH) ? g_qmid[n * HH + c] : g_vnorm[n * HH + (c - HH)];
        sA[r * MXP + c] = v;
    }
    __syncthreads();

    int wid  = tid >> 5;
    int lane = tid & 31;
    int gid  = lane >> 2;
    int tig  = lane & 3;
    int nbase = wid * 48;

    {
        float acc[2][6][4];
        #pragma unroll
        for (int r = 0; r < 2; ++r)
            #pragma unroll
            for (int t = 0; t < 6; ++t)
                #pragma unroll
                for (int c = 0; c < 4; ++c) acc[r][t][c] = 0.f;

        #pragma unroll 1
        for (int k0 = 0; k0 < H2; k0 += 16) {
            int kp = k0 >> 1;
            u32 bh[6][2], bl[6][2];
            #pragma unroll
            for (int t = 0; t < 6; ++t) {
                int col = nbase + t * 8 + gid;
                int i0 = (kp + tig) * H3 + col;
                int i1 = (kp + 4 + tig) * H3 + col;
                bh[t][0] = __ldg(&g_m1h[i0]);
                bh[t][1] = __ldg(&g_m1h[i1]);
                bl[t][0] = __ldg(&g_m1l[i0]);
                bl[t][1] = __ldg(&g_m1l[i1]);
            }
            #pragma unroll
            for (int r = 0; r < 2; ++r) {
                int rb = r * 16;
                float2 f0 = *(const float2*)&sA[(rb + gid)     * MXP + k0 + 2 * tig];
                float2 f1 = *(const float2*)&sA[(rb + gid + 8) * MXP + k0 + 2 * tig];
                float2 f2 = *(const float2*)&sA[(rb + gid)     * MXP + k0 + 8 + 2 * tig];
                float2 f3 = *(const float2*)&sA[(rb + gid + 8) * MXP + k0 + 8 + 2 * tig];
                u32 ah0, al0, ah1, al1, ah2, al2, ah3, al3;
                split_a(f0, ah0, al0); split_a(f1, ah1, al1);
                split_a(f2, ah2, al2); split_a(f3, ah3, al3);
                #pragma unroll
                for (int t = 0; t < 6; ++t) {
                    mma_bf16(acc[r][t][0], acc[r][t][1], acc[r][t][2], acc[r][t][3],
                             ah0, ah1, ah2, ah3, bh[t][0], bh[t][1]);
                    mma_bf16(acc[r][t][0], acc[r][t][1], acc[r][t][2], acc[r][t][3],
                             al0, al1, al2, al3, bh[t][0], bh[t][1]);
                    mma_bf16(acc[r][t][0], acc[r][t][1], acc[r][t][2], acc[r][t][3],
                             ah0, ah1, ah2, ah3, bl[t][0], bl[t][1]);
                }
            }
        }
        #pragma unroll
        for (int r = 0; r < 2; ++r) {
            int row0 = r * 16 + gid;
            int row1 = row0 + 8;
            #pragma unroll
            for (int t = 0; t < 6; ++t) {
                int col = nbase + t * 8 + 2 * tig;
                float b0v = __ldg(&bm1[col]);
                float b1v = __ldg(&bm1[col + 1]);
                sB[row0 * MXP + col]     = silu_f(acc[r][t][0] + b0v);
                sB[row0 * MXP + col + 1] = silu_f(acc[r][t][1] + b1v);
                sB[row1 * MXP + col]     = silu_f(acc[r][t][2] + b0v);
                sB[row1 * MXP + col + 1] = silu_f(acc[r][t][3] + b1v);
            }
        }
    }
    __syncthreads();

    {
        float acc[2][6][4];
        #pragma unroll
        for (int r = 0; r < 2; ++r)
            #pragma unroll
            for (int t = 0; t < 6; ++t)
                #pragma unroll
                for (int c = 0; c < 4; ++c) acc[r][t][c] = 0.f;

        #pragma unroll 1
        for (int k0 = 0; k0 < H3; k0 += 16) {
            int kp = k0 >> 1;
            u32 bh[6][2], bl[6][2];
            #pragma unroll
            for (int t = 0; t < 6; ++t) {
                int col = nbase + t * 8 + gid;
                int i0 = (kp + tig) * H3 + col;
                int i1 = (kp + 4 + tig) * H3 + col;
                bh[t][0] = __ldg(&g_m2h[i0]);
                bh[t][1] = __ldg(&g_m2h[i1]);
                bl[t][0] = __ldg(&g_m2l[i0]);
                bl[t][1] = __ldg(&g_m2l[i1]);
            }
            #pragma unroll
            for (int r = 0; r < 2; ++r) {
                int rb = r * 16;
                float2 f0 = *(const float2*)&sB[(rb + gid)     * MXP + k0 + 2 * tig];
                float2 f1 = *(const float2*)&sB[(rb + gid + 8) * MXP + k0 + 2 * tig];
                float2 f2 = *(const float2*)&sB[(rb + gid)     * MXP + k0 + 8 + 2 * tig];
                float2 f3 = *(const float2*)&sB[(rb + gid + 8) * MXP + k0 + 8 + 2 * tig];
                u32 ah0, al0, ah1, al1, ah2, al2, ah3, al3;
                split_a(f0, ah0, al0); split_a(f1, ah1, al1);
                split_a(f2, ah2, al2); split_a(f3, ah3, al3);
                #pragma unroll
                for (int t = 0; t < 6; ++t) {
                    mma_bf16(acc[r][t][0], acc[r][t][1], acc[r][t][2], acc[r][t][3],
                             ah0, ah1, ah2, ah3, bh[t][0], bh[t][1]);
                    mma_bf16(acc[r][t][0], acc[r][t][1], acc[r][t][2], acc[r][t][3],
                             al0, al1, al2, al3, bh[t][0], bh[t][1]);
                    mma_bf16(acc[r][t][0], acc[r][t][1], acc[r][t][2], acc[r][t][3],
                             ah0, ah1, ah2, ah3, bl[t][0], bl[t][1]);
                }
            }
        }
        __syncthreads();
        #pragma unroll
        for (int r = 0; r < 2; ++r) {
            int row0 = r * 16 + gid;
            int row1 = row0 + 8;
            #pragma unroll
            for (int t = 0; t < 6; ++t) {
                int col = nbase + t * 8 + 2 * tig;
                float b0v = __ldg(&bm2[col]);
                float b1v = __ldg(&bm2[col + 1]);
                sA[row0 * MXP + col]     = acc[r][t][0] + b0v;
                sA[row0 * MXP + col + 1] = acc[r][t][1] + b1v;
                sA[row1 * MXP + col]     = acc[r][t][2] + b0v;
                sA[row1 * MXP + col + 1] = acc[r][t][3] + b1v;
            }
        }
    }
    __syncthreads();

    for (int slot = tid; slot < 32 * HH; slot += 256) {
        int r = slot >> 7;
        int o = slot & 127;
        int n = n0 + r;
        if (n >= NN) break;
        float dq  = sA[r * MXP + o];
        float dms = sA[r * MXP + HH + o];
        float dqm = sA[r * MXP + 2 * HH + o];
        qout[n * HH + o] = g_qmid[n * HH + o] + dq + dqm * g_inner[n * HH + o];
        #pragma unroll
        for (int d = 0; d < 3; ++d) {
            int idx = n * 3 * HH + d * HH + o;
            muout[idx] = g_mumid[idx] + g_muw[idx] * dms;
        }
    }
}

// ---------------- launch ----------------
extern "C" void kernel_launch(void* const* d_in, const int* in_sizes, int n_in,
                              void* d_out, int out_size)
{
    const float* q   = (const float*)d_in[0];
    const float* mu  = (const float*)d_in[1];
    const int*   ei  = (const int*)d_in[2];
    const float* rbf = (const float*)d_in[3];
    const float* uv  = (const float*)d_in[4];
    const float* cut = (const float*)d_in[5];
    const float* Wi1 = (const float*)d_in[6];
    const float* bi1 = (const float*)d_in[7];
    const float* Wi2 = (const float*)d_in[8];
    const float* bi2 = (const float*)d_in[9];
    const float* Wf1 = (const float*)d_in[10];
    const float* bf1 = (const float*)d_in[11];
    const float* Wf2 = (const float*)d_in[12];
    const float* bf2 = (const float*)d_in[13];
    const float* Wv  = (const float*)d_in[14];
    const float* Wm1 = (const float*)d_in[15];
    const float* bm1 = (const float*)d_in[16];
    const float* Wm2 = (const float*)d_in[17];
    const float* bm2 = (const float*)d_in[18];

    float* qout  = (float*)d_out;
    float* muout = qout + (size_t)NN * HH;

    cudaFuncSetAttribute(k_node_mlp, cudaFuncAttributeMaxDynamicSharedMemorySize, NODE_SMEM);
    cudaFuncSetAttribute(k_equiv,    cudaFuncAttributeMaxDynamicSharedMemorySize, EQ_SMEM);
    cudaFuncSetAttribute(k_mix,      cudaFuncAttributeMaxDynamicSharedMemorySize, MIX_SMEM);

    // CSR build + weight splits + mu conversion
    k_zero<<<(NN + 255) / 256, 256>>>();
    k_count<<<512, 256>>>(ei);
    k_mu2h<<<(NN * 3 * HH + 255) / 256, 256>>>(mu);
    {
        u32 *p0, *p1;
        cudaGetSymbolAddress((void**)&p0, g_bhp); cudaGetSymbolAddress((void**)&p1, g_blp);
        k_splitw<<<((HH / 2) * H3 + 255) / 256, 256>>>(Wf2, p0, p1, HH / 2, H3);
        cudaGetSymbolAddress((void**)&p0, g_i1h); cudaGetSymbolAddress((void**)&p1, g_i1l);
        k_splitw<<<((HH / 2) * H3 + 255) / 256, 256>>>(Wi1, p0, p1, HH / 2, H3);
        cudaGetSymbolAddress((void**)&p0, g_i2h); cudaGetSymbolAddress((void**)&p1, g_i2l);
        k_splitw<<<((H3 / 2) * H3 + 255) / 256, 256>>>(Wi2, p0, p1, H3 / 2, H3);
        cudaGetSymbolAddress((void**)&p0, g_vch); cudaGetSymbolAddress((void**)&p1, g_vcl);
        k_splitw<<<((HH / 2) * H2 + 255) / 256, 256>>>(Wv, p0, p1, HH / 2, H2);
        cudaGetSymbolAddress((void**)&p0, g_m1h); cudaGetSymbolAddress((void**)&p1, g_m1l);
        k_splitw<<<((H2 / 2) * H3 + 255) / 256, 256>>>(Wm1, p0, p1, H2 / 2, H3);
        cudaGetSymbolAddress((void**)&p0, g_m2h); cudaGetSymbolAddress((void**)&p1, g_m2l);
        k_splitw<<<((H3 / 2) * H3 + 255) / 256, 256>>>(Wm2, p0, p1, H3 / 2, H3);
    }
    k_scan<<<1, 1024>>>();
    k_fill<<<512, 256>>>(ei);

    // dense stages
    k_node_mlp<<<(NN + 31) / 32, 256, NODE_SMEM>>>(q, bi1, bi2);
    k_edge_filter<<<NE / 64, 256>>>(rbf, cut, Wf1, bf1, bf2);

    // message aggregation
    k_aggregate<<<NN, 128>>>(q, mu, ei, uv);

    // mixing
    k_equiv<<<(NN + 15) / 16, 256, EQ_SMEM>>>();
    k_mix<<<(NN + 31) / 32, 256, MIX_SMEM>>>(bm1, bm2, qout, muout);
}